// round 7
// baseline (speedup 1.0000x reference)
#include <cuda_runtime.h>
#include <cuda_bf16.h>
#include <cstdint>

#define N_MAX 100352
#define E_MAX 1000000
#define HID 64

// ---------------- device scratch ----------------
__device__ float g_H [100000 * HID];
__device__ float g_HW[100000 * HID];
__device__ float g_dinv[N_MAX];
__device__ int   g_hist[N_MAX];
__device__ int   g_offs[N_MAX];
__device__ int   g_cur [N_MAX];
__device__ unsigned long long g_state[256];   // decoupled-lookback state
__device__ int   g_esrc[E_MAX];
__device__ int   g_is64;

// ---------------- edge access ----------------
__device__ __forceinline__ int edge_at(const void* ei, int idx) {
    if (g_is64) return (int)((const long long*)ei)[idx];
    return ((const int*)ei)[idx];
}

// ---------------- zero hist + scan state + dtype detect ----------------
__global__ void k_zero_detect(const unsigned long long* __restrict__ ei, int n) {
    int i = blockIdx.x * blockDim.x + threadIdx.x;
    if (i < n) g_hist[i] = 0;
    if (i < 256) g_state[i] = 0ull;
    if (blockIdx.x == 0) {
        int local = 0;
        for (int j = threadIdx.x; j < 1024; j += blockDim.x)
            if ((ei[j] >> 32) != 0ull) local = 1;
        int any = __syncthreads_or(local);
        if (threadIdx.x == 0) g_is64 = (any == 0);
    }
}

__global__ void k_hist(const void* __restrict__ ei, int E) {
    int e = blockIdx.x * blockDim.x + threadIdx.x;
    if (e < E) atomicAdd(&g_hist[edge_at(ei, E + e)], 1);
}

// ---------------- single-pass scan (decoupled lookback) + dinv ----------
__global__ __launch_bounds__(512) void k_scan_lb(int n) {
    int blk = blockIdx.x;
    int idx = blk * 512 + threadIdx.x;
    int v = (idx < n) ? g_hist[idx] : 0;
    if (idx < n) g_dinv[idx] = rsqrtf((float)v + 1.0f);   // +1 self loop

    int lane = threadIdx.x & 31, wid = threadIdx.x >> 5;
    int inc = v;
    #pragma unroll
    for (int o = 1; o < 32; o <<= 1) {
        int t = __shfl_up_sync(0xffffffffu, inc, o);
        if (lane >= o) inc += t;
    }
    __shared__ int wsum[16];
    if (lane == 31) wsum[wid] = inc;
    __syncthreads();
    if (wid == 0) {
        int s = (lane < 16) ? wsum[lane] : 0;
        #pragma unroll
        for (int o = 1; o < 16; o <<= 1) {
            int t = __shfl_up_sync(0xffffffffu, s, o);
            if (lane >= o) s += t;
        }
        if (lane < 16) wsum[lane] = s;
    }
    __syncthreads();
    int base_local = (wid > 0) ? wsum[wid - 1] : 0;
    int total = wsum[15];

    __shared__ unsigned long long s_prefix;
    if (threadIdx.x == 0) {
        if (blk == 0) {
            atomicExch(&g_state[0], (2ULL << 32) | (unsigned)total);
            s_prefix = 0ull;
        } else {
            atomicExch(&g_state[blk], (1ULL << 32) | (unsigned)total);
            unsigned long long run = 0;
            int j = blk - 1;
            while (true) {
                unsigned long long s = atomicAdd(&g_state[j], 0ULL);
                unsigned st = (unsigned)(s >> 32);
                if (st == 0) { __nanosleep(40); continue; }
                run += (unsigned)s;
                if (st == 2u) break;
                j--;
            }
            atomicExch(&g_state[blk], (2ULL << 32) | (unsigned)(run + total));
            s_prefix = run;
        }
    }
    __syncthreads();
    int excl = (int)(unsigned)s_prefix + base_local + inc - v;
    if (idx < n) { g_offs[idx] = excl; g_cur[idx] = excl; }
}

__global__ void k_place(const void* __restrict__ ei, int E) {
    int e = blockIdx.x * blockDim.x + threadIdx.x;
    if (e < E) {
        int s = edge_at(ei, e);
        int d = edge_at(ei, E + e);
        int pos = atomicAdd(&g_cur[d], 1);
        g_esrc[pos] = s;
    }
}

// ---------------- bf16 split helpers ----------------
__device__ __forceinline__ unsigned short bits_of(__nv_bfloat16 h) {
    return *(unsigned short*)&h;
}
__device__ __forceinline__ void split2(float x, float y, unsigned& hi, unsigned& lo) {
    __nv_bfloat16 hx = __float2bfloat16_rn(x);
    __nv_bfloat16 hy = __float2bfloat16_rn(y);
    __nv_bfloat16 lx = __float2bfloat16_rn(x - __bfloat162float(hx));
    __nv_bfloat16 ly = __float2bfloat16_rn(y - __bfloat162float(hy));
    hi = (unsigned)bits_of(hx) | ((unsigned)bits_of(hy) << 16);
    lo = (unsigned)bits_of(lx) | ((unsigned)bits_of(ly) << 16);
}

__device__ __forceinline__ void mma16816(float* c, const unsigned* a,
                                         unsigned b0, unsigned b1) {
    asm volatile(
        "mma.sync.aligned.m16n8k16.row.col.f32.bf16.bf16.f32 "
        "{%0,%1,%2,%3}, {%4,%5,%6,%7}, {%8,%9}, {%0,%1,%2,%3};"
        : "+f"(c[0]), "+f"(c[1]), "+f"(c[2]), "+f"(c[3])
        : "r"(a[0]), "r"(a[1]), "r"(a[2]), "r"(a[3]), "r"(b0), "r"(b1));
}

// ---------------- tensor GEMM: C[n,64] = A[n,K] @ W[K,64] (+bias) --------
__global__ __launch_bounds__(256) void k_tgemm(
    const float* __restrict__ Aext, const float* __restrict__ W,
    const float* __restrict__ bias, float* __restrict__ out_ext,
    int dst, int n, int K)
{
    const float* A = Aext ? Aext : (const float*)g_H;
    float* C = (dst == 0) ? (float*)g_H : (dst == 1) ? (float*)g_HW : out_ext;

    __shared__ __nv_bfloat16 Wh[64][72];
    __shared__ __nv_bfloat16 Wl[64][72];

    int tid = threadIdx.x;
    if (K == 64) {
        #pragma unroll
        for (int u = 0; u < 16; u++) {
            int i = tid * 16 + u;
            int kk = i >> 6, nn = i & 63;
            float wv = W[i];
            __nv_bfloat16 h = __float2bfloat16_rn(wv);
            __nv_bfloat16 l = __float2bfloat16_rn(wv - __bfloat162float(h));
            Wh[nn][kk] = h; Wl[nn][kk] = l;
        }
    }

    int row_base = blockIdx.x * 128;
    int warp = tid >> 5, lane = tid & 31;
    int r = lane >> 2, q = lane & 3;
    int row0 = row_base + warp * 16 + r;
    int rowA0 = min(row0, n - 1);
    int rowA1 = min(row0 + 8, n - 1);

    float c[8][4];
    #pragma unroll
    for (int nf = 0; nf < 8; nf++)
        #pragma unroll
        for (int j = 0; j < 4; j++) c[nf][j] = 0.0f;

    int khalves = K >> 6;
    for (int kh = 0; kh < khalves; kh++) {
        if (K == 128) {
            __syncthreads();
            for (int i = tid; i < 64 * 64; i += 256) {
                int kk = i >> 6, nn = i & 63;
                float wv = W[(kh * 64 + kk) * 64 + nn];
                __nv_bfloat16 h = __float2bfloat16_rn(wv);
                __nv_bfloat16 l = __float2bfloat16_rn(wv - __bfloat162float(h));
                Wh[nn][kk] = h; Wl[nn][kk] = l;
            }
        }
        __syncthreads();

        #pragma unroll
        for (int kc = 0; kc < 4; kc++) {
            int kbase = kh * 64 + kc * 16 + q * 2;
            const float* p0 = A + (size_t)rowA0 * K + kbase;
            const float* p1 = A + (size_t)rowA1 * K + kbase;
            float2 v0 = *(const float2*)p0;
            float2 v1 = *(const float2*)p1;
            float2 v2 = *(const float2*)(p0 + 8);
            float2 v3 = *(const float2*)(p1 + 8);
            unsigned ah[4], al[4];
            split2(v0.x, v0.y, ah[0], al[0]);
            split2(v1.x, v1.y, ah[1], al[1]);
            split2(v2.x, v2.y, ah[2], al[2]);
            split2(v3.x, v3.y, ah[3], al[3]);

            #pragma unroll
            for (int nf = 0; nf < 8; nf++) {
                int bn = nf * 8 + r;
                int bk = kc * 16 + q * 2;
                unsigned bh0 = *(const unsigned*)&Wh[bn][bk];
                unsigned bh1 = *(const unsigned*)&Wh[bn][bk + 8];
                unsigned bl0 = *(const unsigned*)&Wl[bn][bk];
                unsigned bl1 = *(const unsigned*)&Wl[bn][bk + 8];
                mma16816(c[nf], ah, bh0, bh1);
                mma16816(c[nf], al, bh0, bh1);
                mma16816(c[nf], ah, bl0, bl1);
            }
        }
    }

    #pragma unroll
    for (int nf = 0; nf < 8; nf++) {
        int col = nf * 8 + q * 2;
        float bx = 0.f, by = 0.f;
        if (bias) { float2 bb = *(const float2*)(bias + col); bx = bb.x; by = bb.y; }
        if (row0 < n)
            *(float2*)(C + (size_t)row0 * 64 + col) =
                make_float2(c[nf][0] + bx, c[nf][1] + by);
        if (row0 + 8 < n)
            *(float2*)(C + (size_t)(row0 + 8) * 64 + col) =
                make_float2(c[nf][2] + bx, c[nf][3] + by);
    }
}

// ---------------- fused aggregate + bias + LN (+ReLU+residual) ----------
// one warp per node; 4 independent gather chains for MLP
__global__ void k_agg(const float* __restrict__ bias, const float* __restrict__ gma,
                      const float* __restrict__ beta, float* __restrict__ out_ext,
                      int n, int relu_res)
{
    int node = (blockIdx.x * blockDim.x + threadIdx.x) >> 5;
    if (node >= n) return;
    int lane = threadIdx.x & 31;
    float* out = out_ext ? out_ext : (float*)g_H;

    float di = g_dinv[node];
    // acc = di*hw[node] + sum dinv[s]*hw[s]; final scaled by di
    float2 a0 = ((const float2*)(g_HW + (size_t)node * HID))[lane];
    a0.x *= di; a0.y *= di;
    float2 a1 = make_float2(0.f, 0.f), a2 = a1, a3 = a1;

    int e = g_offs[node];
    int e_end = e + g_hist[node];
    for (; e + 4 <= e_end; e += 4) {
        int s0 = g_esrc[e],     s1 = g_esrc[e + 1];
        int s2 = g_esrc[e + 2], s3 = g_esrc[e + 3];
        float n0 = g_dinv[s0], n1 = g_dinv[s1], n2 = g_dinv[s2], n3 = g_dinv[s3];
        float2 v0 = ((const float2*)(g_HW + (size_t)s0 * HID))[lane];
        float2 v1 = ((const float2*)(g_HW + (size_t)s1 * HID))[lane];
        float2 v2 = ((const float2*)(g_HW + (size_t)s2 * HID))[lane];
        float2 v3 = ((const float2*)(g_HW + (size_t)s3 * HID))[lane];
        a0.x = fmaf(v0.x, n0, a0.x); a0.y = fmaf(v0.y, n0, a0.y);
        a1.x = fmaf(v1.x, n1, a1.x); a1.y = fmaf(v1.y, n1, a1.y);
        a2.x = fmaf(v2.x, n2, a2.x); a2.y = fmaf(v2.y, n2, a2.y);
        a3.x = fmaf(v3.x, n3, a3.x); a3.y = fmaf(v3.y, n3, a3.y);
    }
    for (; e < e_end; e++) {
        int s0 = g_esrc[e];
        float n0 = g_dinv[s0];
        float2 v0 = ((const float2*)(g_HW + (size_t)s0 * HID))[lane];
        a0.x = fmaf(v0.x, n0, a0.x); a0.y = fmaf(v0.y, n0, a0.y);
    }
    float2 acc = make_float2((a0.x + a1.x) + (a2.x + a3.x),
                             (a0.y + a1.y) + (a2.y + a3.y));
    acc.x *= di; acc.y *= di;

    float2 bb = ((const float2*)bias)[lane];
    acc.x += bb.x; acc.y += bb.y;

    float sum = acc.x + acc.y;
    #pragma unroll
    for (int o = 16; o; o >>= 1) sum += __shfl_xor_sync(0xffffffffu, sum, o);
    float mu = sum * (1.0f / 64.0f);
    float dx = acc.x - mu, dy = acc.y - mu;
    float vs = dx * dx + dy * dy;
    #pragma unroll
    for (int o = 16; o; o >>= 1) vs += __shfl_xor_sync(0xffffffffu, vs, o);
    float rstd = rsqrtf(vs * (1.0f / 64.0f) + 1e-5f);
    float2 gg = ((const float2*)gma)[lane];
    float2 be = ((const float2*)beta)[lane];
    float ox = dx * rstd * gg.x + be.x;
    float oy = dy * rstd * gg.y + be.y;

    if (relu_res) {
        float2 rr = ((const float2*)(g_H + (size_t)node * HID))[lane];
        ox = fmaxf(ox, 0.0f) + rr.x;
        oy = fmaxf(oy, 0.0f) + rr.y;
    }
    ((float2*)(out + (size_t)node * HID))[lane] = make_float2(ox, oy);
}

// ---------------- launch ----------------
extern "C" void kernel_launch(void* const* d_in, const int* in_sizes, int n_in,
                              void* d_out, int out_size)
{
    const float* x      = (const float*)d_in[0];
    const void*  ei     = d_in[1];
    const float* proj_w = (const float*)d_in[2];
    const float* proj_b = (const float*)d_in[3];
    const float* w[3]  = { (const float*)d_in[4],  (const float*)d_in[8],  (const float*)d_in[12] };
    const float* b[3]  = { (const float*)d_in[5],  (const float*)d_in[9],  (const float*)d_in[13] };
    const float* gm[3] = { (const float*)d_in[6],  (const float*)d_in[10], (const float*)d_in[14] };
    const float* bt[3] = { (const float*)d_in[7],  (const float*)d_in[11], (const float*)d_in[15] };

    int n = in_sizes[0] / 128;    // 100000
    int E = in_sizes[1] / 2;      // 1000000
    float* out = (float*)d_out;

    int nb512 = (n + 511) / 512;
    int gemm_blocks = (n + 127) / 128;

    k_zero_detect<<<(n + 255) / 256, 256>>>((const unsigned long long*)ei, n);    // 0
    k_hist<<<(E + 255) / 256, 256>>>(ei, E);                                       // 1
    k_scan_lb<<<nb512, 512>>>(n);                                                  // 2
    k_tgemm<<<gemm_blocks, 256>>>(x, proj_w, proj_b, nullptr, /*dst=*/0, n, 128);  // 3 <- profiled
    k_place<<<(E + 255) / 256, 256>>>(ei, E);                                      // 4

    int agg_blocks = (n + 7) / 8;
    for (int l = 0; l < 3; l++) {
        k_tgemm<<<gemm_blocks, 256>>>(nullptr, w[l], nullptr, nullptr, /*dst=*/1, n, 64);
        float* dst = (l < 2) ? nullptr : out;
        k_agg<<<agg_blocks, 256>>>(b[l], gm[l], bt[l], dst, n, (l < 2) ? 1 : 0);
    }
}